// round 15
// baseline (speedup 1.0000x reference)
#include <cuda_runtime.h>
#include <cuda_fp16.h>
#include <math.h>
#include <stdint.h>

#define E_ 400000
#define NN_ 50000
#define B_ 50

// ---------------- device scratch (no allocs allowed) ----------------
__device__ float g_mail[NN_ * 64];
__device__ float g_ecomb[B_ * 64];
__device__ float g_ncomb[B_ * 64];
__device__ float g_gbias_e[B_ * 256];
__device__ float g_gbias_n[B_ * 256];
// fp16 weights, rows PERMUTED to d-major (r = d*4+gate), stored PRE-SWIZZLED
// (SW128) per (half, chunk) 16KB block for bulk copy.
__device__ __align__(128) __half g_W_e[256 * 256];   // 8 blocks of 8192
__device__ __align__(128) __half g_W_n[256 * 192];   // 6 blocks of 8192
// fp16 activations (single rounding)
__device__ __align__(16) __half g_nf[NN_ * 64];
__device__ __align__(16) __half g_nh[NN_ * 64];
__device__ __align__(16) __half g_ml[NN_ * 64];
__device__ __align__(16) __half g_ef[E_ * 64];
__device__ __align__(16) __half g_eh[E_ * 64];

// ---------------- smem layout (bytes) ----------------
#define OFF_BIAS 0                     // 128 f32 (permuted bias, this half)
#define OFF_RSUM 512                   // 64 f32
#define OFF_GB   768                   // 2 x 128 f32 (permuted gbias)
#define OFF_MBAR 1792                  // 2 mbarriers
#define OFF_A    3712                  // A[buf]: 64*144 = 9216 each
#define ABUF(buf) (OFF_A + (buf) * 9216)
#define OFF_B    22528                 // B[buf]: 16384 each (1KB aligned)
#define BBUF(buf) (OFF_B + (buf) * 16384)
#define SMEM_SZ  55296
#define BCHUNK_BYTES 16384

// ---------------- PTX helpers (baseline PTX only) ----------------
__device__ __forceinline__ uint32_t smem_u32(const void* p) {
    uint32_t a;
    asm("{ .reg .u64 t; cvta.to.shared.u64 t, %1; cvt.u32.u64 %0, t; }" : "=r"(a) : "l"(p));
    return a;
}
#define CP_ASYNC16(dst, src) \
    asm volatile("cp.async.ca.shared.global [%0], [%1], 16;" :: "r"(dst), "l"(src))
#define CP_COMMIT() asm volatile("cp.async.commit_group;" ::: "memory")
#define CP_WAIT0()  asm volatile("cp.async.wait_group 0;" ::: "memory")

#define MBARRIER_INIT(addr, cnt) \
    asm volatile("mbarrier.init.shared.b64 [%0], %1;" :: "r"((uint32_t)(addr)), "r"((uint32_t)(cnt)) : "memory")
#define MBARRIER_EXPECT_TX(addr, bytes) \
    asm volatile("mbarrier.arrive.expect_tx.shared.b64 _, [%0], %1;" :: "r"((uint32_t)(addr)), "r"((uint32_t)(bytes)) : "memory")
#define CP_BULK(dst, src, sz, mbar) \
    asm volatile("cp.async.bulk.shared::cta.global.mbarrier::complete_tx::bytes [%0], [%1], %2, [%3];" \
        :: "r"((uint32_t)(dst)), "l"(src), "r"((uint32_t)(sz)), "r"((uint32_t)(mbar)) : "memory")
#define MBAR_WAIT(addr, parity) do { \
    uint32_t _m = (uint32_t)(addr); uint32_t _p = (uint32_t)(parity); uint32_t _d; \
    asm volatile("{ .reg .pred p; mbarrier.try_wait.parity.shared.b64 p, [%1], %2; selp.b32 %0, 1, 0, p; }" \
        : "=r"(_d) : "r"(_m), "r"(_p) : "memory"); \
    if (!_d) { \
        asm volatile("{ .reg .pred P1; WL_%=: mbarrier.try_wait.parity.shared.b64 P1, [%0], %1; @P1 bra.uni WD_%=; bra.uni WL_%=; WD_%=: }" \
            :: "r"(_m), "r"(_p) : "memory"); \
    } } while (0)

__device__ __forceinline__ void ldsm4(uint32_t* r, uint32_t a) {
    asm volatile("ldmatrix.sync.aligned.m8n8.x4.shared.b16 {%0,%1,%2,%3}, [%4];"
        : "=r"(r[0]), "=r"(r[1]), "=r"(r[2]), "=r"(r[3]) : "r"(a));
}
__device__ __forceinline__ void mma16816(float* d, const uint32_t* a, uint32_t b0, uint32_t b1) {
    asm volatile("mma.sync.aligned.m16n8k16.row.col.f32.f16.f16.f32 "
        "{%0,%1,%2,%3},{%4,%5,%6,%7},{%8,%9},{%0,%1,%2,%3};"
        : "+f"(d[0]), "+f"(d[1]), "+f"(d[2]), "+f"(d[3])
        : "r"(a[0]), "r"(a[1]), "r"(a[2]), "r"(a[3]), "r"(b0), "r"(b1));
}

// ---------------- math helpers ----------------
__device__ __forceinline__ float sigm(float x) { return 1.0f / (1.0f + __expf(-x)); }
__device__ __forceinline__ float tanh_(float x) {
    return __fdividef(2.0f, 1.0f + __expf(-2.0f * x)) - 1.0f;
}

// ---------------- staging ----------------
// A chunk: 64 rows x 64 k fp16, padded rows. 2 cp.async per thread.
template <int MODE>
__device__ __forceinline__ void issue_A(uint32_t smb, int oa,
    int s, int m0, int Mrows, int tid,
    const int* __restrict__ srcI, const int* __restrict__ dstI)
{
    #pragma unroll
    for (int t = 0; t < 2; ++t) {
        int idx = tid + t * 256;
        int rl = idx >> 3, q = idx & 7;
        int grow = m0 + rl;
        if (grow >= Mrows) grow = Mrows - 1;
        const __half* base;
        size_t ridx;
        if (MODE == 0) {
            if (s == 0)      { base = g_ef; ridx = (size_t)grow; }
            else if (s == 1) { base = g_nf; ridx = (size_t)srcI[grow]; }
            else if (s == 2) { base = g_nf; ridx = (size_t)dstI[grow]; }
            else             { base = g_eh; ridx = (size_t)grow; }
        } else {
            if (s == 0)      base = g_nf;
            else if (s == 1) base = g_ml;
            else             base = g_nh;
            ridx = (size_t)grow;
        }
        CP_ASYNC16(smb + oa + rl * 144 + q * 16,
                   (const char*)(base + ridx * 64 + q * 8));
    }
}

// single-pass fp16 mma over one K=64 chunk; warp tile 32 rows x 32 cols
__device__ __forceinline__ void compute64(uint32_t smb, int aB, int bB,
                                          uint32_t aoff, uint32_t bbase,
                                          uint32_t bcx, uint32_t xterm,
                                          float (&acc)[2][4][4])
{
    #pragma unroll
    for (int kt = 0; kt < 4; ++kt) {
        const uint32_t bco = (bcx + kt * 32) ^ xterm;
        uint32_t b4[2][4];
        #pragma unroll
        for (int g = 0; g < 2; ++g) ldsm4(b4[g], smb + bB + bbase + g * 2048 + bco);
        #pragma unroll
        for (int mt = 0; mt < 2; ++mt) {
            uint32_t a[4];
            ldsm4(a, smb + aB + aoff + mt * 2304 + kt * 32);
            #pragma unroll
            for (int g = 0; g < 2; ++g) {
                mma16816(acc[mt][2 * g],     a, b4[g][0], b4[g][2]);
                mma16816(acc[mt][2 * g + 1], a, b4[g][1], b4[g][3]);
            }
        }
    }
}

// MODE 0: edge (K=256), MODE 1: node (K=192).
// CTA = 64 rows x 128 permuted gate-cols (half h covers d in [h*32, h*32+32)).
template <int MODE>
__global__ void __launch_bounds__(256, 3)
lstm_mma_kernel(const float* __restrict__ c_in,
                const float* __restrict__ bih,
                const float* __restrict__ bhh,
                const int* __restrict__ srcI,
                const int* __restrict__ dstI,
                const int* __restrict__ rgraph,
                float* __restrict__ out_r,
                float* __restrict__ out_h,
                float* __restrict__ out_c,
                int Mrows)
{
    constexpr int KTOT = (MODE == 0) ? 256 : 192;
    constexpr int NC = KTOT / 64;
    extern __shared__ char sm[];
    const uint32_t smb = smem_u32(sm);
    float* bias_s = (float*)(sm + OFF_BIAS);
    float* rsum   = (float*)(sm + OFF_RSUM);
    float* gb_s   = (float*)(sm + OFF_GB);

    const int tid = threadIdx.x;
    const int lane = tid & 31;
    const int wid = tid >> 5;
    const int m0 = (blockIdx.x >> 1) * 64;
    const int h = blockIdx.x & 1;
    const __half* W = ((MODE == 0) ? g_W_e : g_W_n) + (size_t)h * NC * 8192;
    const float* gbias = (MODE == 0) ? g_gbias_e : g_gbias_n;

    if (tid == 0) {
        MBARRIER_INIT(smb + OFF_MBAR, 1);
        MBARRIER_INIT(smb + OFF_MBAR + 8, 1);
    }
    // permuted bias for this half: bias_s[dl*4+gate]
    if (tid < 128) {
        int gate = tid & 3, dl = tid >> 2;
        bias_s[tid] = bih[gate * 64 + h * 32 + dl] + bhh[gate * 64 + h * 32 + dl];
    }
    if (tid < 64) rsum[tid] = 0.f;

    const int gfirst = rgraph[m0];
    int mlast = (m0 + 63 < Mrows) ? (m0 + 63) : (Mrows - 1);
    const int glast = rgraph[mlast];
    {   // permuted gbias: gb_s[sel*128 + dl*4+gate]
        int sel = tid >> 7, t2 = tid & 127;
        int gate = t2 & 3, dl = t2 >> 2;
        gb_s[tid] = gbias[(size_t)(sel ? glast : gfirst) * 256 + gate * 64 + h * 32 + dl];
    }
    __syncthreads();

    // prologue: chunk 0
    issue_A<MODE>(smb, ABUF(0), 0, m0, Mrows, tid, srcI, dstI);
    CP_COMMIT();
    if (tid == 0) {
        MBARRIER_EXPECT_TX(smb + OFF_MBAR, BCHUNK_BYTES);
        CP_BULK(smb + BBUF(0), (const char*)W, BCHUNK_BYTES, smb + OFF_MBAR);
    }
    CP_WAIT0();
    MBAR_WAIT(smb + OFF_MBAR, 0);
    __syncthreads();

    float acc[2][4][4];
    #pragma unroll
    for (int i = 0; i < 2; ++i)
        #pragma unroll
        for (int j = 0; j < 4; ++j)
            #pragma unroll
            for (int k = 0; k < 4; ++k) acc[i][j][k] = 0.f;

    const int wm = wid & 1, wn = wid >> 1;    // 2 x 4 warp grid; warp tile 32x32
    const uint32_t aoff  = (uint32_t)((wm * 32 + (lane & 15)) * 144 + (lane >> 4) * 16);
    const uint32_t bbase = (uint32_t)((wn * 32 + (lane & 15)) * 128);
    const uint32_t bcx   = (uint32_t)((lane >> 4) * 16);
    const uint32_t xterm = (uint32_t)((lane & 7) << 4);

    #pragma unroll 1
    for (int c = 0; c < NC; ++c) {
        const int cur = c & 1, nxt = cur ^ 1;
        const bool have_next = (c + 1 < NC);
        if (have_next) {
            issue_A<MODE>(smb, ABUF(nxt), c + 1, m0, Mrows, tid, srcI, dstI);
            CP_COMMIT();
            if (tid == 0) {
                MBARRIER_EXPECT_TX(smb + OFF_MBAR + 8 * nxt, BCHUNK_BYTES);
                CP_BULK(smb + BBUF(nxt),
                        (const char*)W + (size_t)(c + 1) * BCHUNK_BYTES,
                        BCHUNK_BYTES, smb + OFF_MBAR + 8 * nxt);
            }
        }
        compute64(smb, ABUF(cur), BBUF(cur), aoff, bbase, bcx, xterm, acc);
        if (have_next) {
            CP_WAIT0();
            MBAR_WAIT(smb + OFF_MBAR + 8 * nxt, ((c + 1) >> 1) & 1);
        }
        __syncthreads();
    }

    // ---- register epilogue: shfl-exchange gate pairs; no smem round-trip ----
    // lane pair (x, x^1): even lane ends with full gates at row r, odd at row r+8.
    const int sub = lane & 3;
    const int rhalf = lane & 1;
    const int rbase = wm * 32 + (lane >> 2) + rhalf * 8;
    #pragma unroll
    for (int nt = 0; nt < 4; ++nt) {
        const int dloc = wn * 8 + nt * 2 + (sub >> 1);
        const int d = h * 32 + dloc;
        const float4 bb = *(float4*)&bias_s[dloc * 4];
        const float4 q0 = *(float4*)&gb_s[dloc * 4];
        const float4 q1 = *(float4*)&gb_s[128 + dloc * 4];
        float s0 = 0.f, s1 = 0.f;
        #pragma unroll
        for (int mt = 0; mt < 2; ++mt) {
            float x0 = __shfl_xor_sync(0xffffffffu, acc[mt][nt][0], 1);
            float x1 = __shfl_xor_sync(0xffffffffu, acc[mt][nt][1], 1);
            float x2 = __shfl_xor_sync(0xffffffffu, acc[mt][nt][2], 1);
            float x3 = __shfl_xor_sync(0xffffffffu, acc[mt][nt][3], 1);
            float gi, gf, gg, go;
            if (rhalf == 0) { gi = acc[mt][nt][0]; gf = acc[mt][nt][1]; gg = x0; go = x1; }
            else            { gi = x2; gf = x3; gg = acc[mt][nt][2]; go = acc[mt][nt][3]; }
            int grow = m0 + rbase + mt * 16;
            if (grow < Mrows) {
                bool first = (rgraph[grow] == gfirst);
                gi += bb.x + (first ? q0.x : q1.x);
                gf += bb.y + (first ? q0.y : q1.y);
                gg += bb.z + (first ? q0.z : q1.z);
                go += bb.w + (first ? q0.w : q1.w);
                float c2 = sigm(gf) * c_in[(size_t)grow * 64 + d] + sigm(gi) * tanh_(gg);
                float hh = sigm(go) * tanh_(c2);
                float r = fmaxf(hh, 0.f);
                out_r[(size_t)grow * 64 + d] = r;
                out_h[(size_t)grow * 64 + d] = hh;
                out_c[(size_t)grow * 64 + d] = c2;
                if (MODE == 0) atomicAdd(&g_mail[(size_t)dstI[grow] * 64 + d], r);
                if (first) s0 += r; else s1 += r;
            }
        }
        atomicAdd(&rsum[dloc], s0);
        if (glast != gfirst) atomicAdd(&rsum[32 + dloc], s1);
    }
    __syncthreads();
    float* comb = (MODE == 0) ? g_ecomb : g_ncomb;
    if (tid < 32) atomicAdd(&comb[(size_t)gfirst * 64 + h * 32 + tid], rsum[tid]);
    else if (tid < 64 && glast != gfirst)
        atomicAdd(&comb[(size_t)glast * 64 + h * 32 + (tid - 32)], rsum[tid]);
}

// ---------------- prep kernels ----------------
__device__ __forceinline__ uint2 cvt4(float4 v) {
    __half2 h01 = __floats2half2_rn(v.x, v.y);
    __half2 h23 = __floats2half2_rn(v.z, v.w);
    uint2 r;
    r.x = *(uint32_t*)&h01;
    r.y = *(uint32_t*)&h23;
    return r;
}

// fused: convert ef/eh/nf/nh to fp16 (vectorized x4) + zero scratch
__global__ void prep_kernel(const float* __restrict__ ef, const float* __restrict__ eh,
                            const float* __restrict__ nf, const float* __restrict__ nh)
{
    size_t i4 = ((size_t)blockIdx.x * 256 + threadIdx.x) * 4;
    if (i4 < (size_t)E_ * 64) {
        *(uint2*)(g_ef + i4) = cvt4(*(const float4*)(ef + i4));
        *(uint2*)(g_eh + i4) = cvt4(*(const float4*)(eh + i4));
    }
    if (i4 < (size_t)NN_ * 64) {
        *(uint2*)(g_nf + i4) = cvt4(*(const float4*)(nf + i4));
        *(uint2*)(g_nh + i4) = cvt4(*(const float4*)(nh + i4));
        *(float4*)(g_mail + i4) = make_float4(0.f, 0.f, 0.f, 0.f);
    }
    if (i4 < B_ * 64) {
        *(float4*)(g_ecomb + i4) = make_float4(0.f, 0.f, 0.f, 0.f);
        *(float4*)(g_ncomb + i4) = make_float4(0.f, 0.f, 0.f, 0.f);
    }
}

// W -> fp16, rows permuted to d-major (r = d*4+gate), pre-swizzled per
// (half, chunk) 16KB block: block = h*NC + c.
__global__ void splitw_kernel(const float* __restrict__ Wih_e, const float* __restrict__ Whh_e,
                              const float* __restrict__ Wih_n, const float* __restrict__ Whh_n)
{
    int i = blockIdx.x * 256 + threadIdx.x;
    if (i < 256 * 256) {
        int go = i >> 8, k = i & 255;
        float v = (k < 192) ? Wih_e[go * 256 + k] : Whh_e[go * 64 + (k - 192)];
        int gate = go >> 6, d = go & 63;
        int r = d * 4 + gate;
        int hh = r >> 7, rr = r & 127;
        int c = k >> 6, kl = k & 63;
        uint32_t off = (uint32_t)(rr * 128 + kl * 2);
        uint32_t sw = off ^ ((off >> 3) & 0x70);
        g_W_e[(hh * 4 + c) * 8192 + (sw >> 1)] = __float2half_rn(v);
    }
    if (i < 256 * 192) {
        int go = i / 192, k = i - go * 192;
        float v = (k < 128) ? Wih_n[go * 192 + k] : Whh_n[go * 64 + (k - 128)];
        int gate = go >> 6, d = go & 63;
        int r = d * 4 + gate;
        int hh = r >> 7, rr = r & 127;
        int c = k >> 6, kl = k & 63;
        uint32_t off = (uint32_t)(rr * 128 + kl * 2);
        uint32_t sw = off ^ ((off >> 3) & 0x70);
        g_W_n[(hh * 3 + c) * 8192 + (sw >> 1)] = __float2half_rn(v);
    }
}

// per-graph gate bias: grepr @ Wseg (f32, exact; unpermuted — kernel permutes on load)
__global__ void gbias_kernel(const float* __restrict__ grepr,
                             const float* __restrict__ Wih_e,
                             const float* __restrict__ Wih_n)
{
    __shared__ float gsh[64];
    const int b = blockIdx.x, tid = threadIdx.x;
    if (tid < 64) gsh[tid] = grepr[b * 64 + tid];
    __syncthreads();
    float ae = 0.f, an = 0.f;
    #pragma unroll 8
    for (int k = 0; k < 64; ++k) {
        ae += gsh[k] * Wih_e[tid * 256 + 192 + k];
        an += gsh[k] * Wih_n[tid * 192 + 128 + k];
    }
    g_gbias_e[b * 256 + tid] = ae;
    g_gbias_n[b * 256 + tid] = an;
}

__global__ void split_mail_kernel()
{
    size_t i4 = ((size_t)blockIdx.x * 256 + threadIdx.x) * 4;
    if (i4 < (size_t)NN_ * 64)
        *(uint2*)(g_ml + i4) = cvt4(*(const float4*)(g_mail + i4));
}

// ---------------- graph-level LSTM (B=50) ----------------
__global__ void graph_lstm_kernel(
    const float* __restrict__ grepr,
    const float* __restrict__ h_in,
    const float* __restrict__ c_in,
    const float* __restrict__ Wih,
    const float* __restrict__ Whh,
    const float* __restrict__ bih,
    const float* __restrict__ bhh,
    float* __restrict__ out_r,
    float* __restrict__ out_h,
    float* __restrict__ out_c)
{
    __shared__ float xu[256];
    __shared__ float gs[256];
    const int b = blockIdx.x;
    const int tid = threadIdx.x;

    if (tid < 64)       xu[tid] = g_ncomb[b * 64 + tid];
    else if (tid < 128) xu[tid] = g_ecomb[b * 64 + (tid - 64)];
    else if (tid < 192) xu[tid] = grepr[b * 64 + (tid - 128)];
    else                xu[tid] = h_in[b * 64 + (tid - 192)];
    __syncthreads();

    float a = bih[tid] + bhh[tid];
    const float* wih_row = Wih + (size_t)tid * 192;
    #pragma unroll 8
    for (int k4 = 0; k4 < 48; ++k4) {
        float4 w = *(const float4*)&wih_row[k4 * 4];
        a += w.x * xu[k4 * 4] + w.y * xu[k4 * 4 + 1] + w.z * xu[k4 * 4 + 2] + w.w * xu[k4 * 4 + 3];
    }
    const float* whh_row = Whh + (size_t)tid * 64;
    #pragma unroll 8
    for (int k4 = 0; k4 < 16; ++k4) {
        float4 w = *(const float4*)&whh_row[k4 * 4];
        a += w.x * xu[192 + k4 * 4] + w.y * xu[192 + k4 * 4 + 1]
           + w.z * xu[192 + k4 * 4 + 2] + w.w * xu[192 + k4 * 4 + 3];
    }
    gs[tid] = a;
    __syncthreads();

    if (tid < 64) {
        float gi = gs[tid], gf = gs[64 + tid], gg = gs[128 + tid], go = gs[192 + tid];
        float c2 = sigm(gf) * c_in[b * 64 + tid] + sigm(gi) * tanh_(gg);
        float h = sigm(go) * tanh_(c2);
        out_r[b * 64 + tid] = fmaxf(h, 0.f);
        out_h[b * 64 + tid] = h;
        out_c[b * 64 + tid] = c2;
    }
}

extern "C" void kernel_launch(void* const* d_in, const int* in_sizes, int n_in,
                              void* d_out, int out_size)
{
    const float* edge_feat  = (const float*)d_in[0];
    const float* node_feat  = (const float*)d_in[1];
    const float* g_repr     = (const float*)d_in[2];
    const float* edge_h     = (const float*)d_in[3];
    const float* edge_c     = (const float*)d_in[4];
    const float* node_h     = (const float*)d_in[5];
    const float* node_c     = (const float*)d_in[6];
    const float* graph_h    = (const float*)d_in[7];
    const float* graph_c    = (const float*)d_in[8];
    const float* Wih_e      = (const float*)d_in[9];
    const float* Whh_e      = (const float*)d_in[10];
    const float* bih_e      = (const float*)d_in[11];
    const float* bhh_e      = (const float*)d_in[12];
    const float* Wih_n      = (const float*)d_in[13];
    const float* Whh_n      = (const float*)d_in[14];
    const float* bih_n      = (const float*)d_in[15];
    const float* bhh_n      = (const float*)d_in[16];
    const float* Wih_u      = (const float*)d_in[17];
    const float* Whh_u      = (const float*)d_in[18];
    const float* bih_u      = (const float*)d_in[19];
    const float* bhh_u      = (const float*)d_in[20];
    const int*   src        = (const int*)d_in[21];
    const int*   dst        = (const int*)d_in[22];
    const int*   edge_graph = (const int*)d_in[23];
    const int*   node_graph = (const int*)d_in[24];

    float* out = (float*)d_out;
    const size_t ED = (size_t)E_ * 64;
    const size_t ND = (size_t)NN_ * 64;
    const size_t BD = (size_t)B_ * 64;
    float* e_out = out;
    float* h_e   = out + ED;
    float* c_e   = out + 2 * ED;
    float* n_out = out + 3 * ED;
    float* h_n   = n_out + ND;
    float* c_n   = n_out + 2 * ND;
    float* u_out = n_out + 3 * ND;
    float* h_u   = u_out + BD;
    float* c_u   = u_out + 2 * BD;

    cudaFuncSetAttribute(lstm_mma_kernel<0>, cudaFuncAttributeMaxDynamicSharedMemorySize, SMEM_SZ);
    cudaFuncSetAttribute(lstm_mma_kernel<1>, cudaFuncAttributeMaxDynamicSharedMemorySize, SMEM_SZ);

    // 1) prep
    prep_kernel<<<(int)(((size_t)E_ * 64 / 4 + 255) / 256), 256>>>(edge_feat, edge_h, node_feat, node_h);
    splitw_kernel<<<256, 256>>>(Wih_e, Whh_e, Wih_n, Whh_n);
    gbias_kernel<<<B_, 256>>>(g_repr, Wih_e, Wih_n);

    // 2) edge LSTM (half-gate CTAs, 3 CTA/SM, register epilogue) + mailbox + e_comb
    lstm_mma_kernel<0><<<(E_ / 64) * 2, 256, SMEM_SZ>>>(
        edge_c, bih_e, bhh_e, src, dst, edge_graph, e_out, h_e, c_e, E_);

    // 3) convert mail, then node LSTM + n_comb
    split_mail_kernel<<<(NN_ * 64 / 4 + 255) / 256, 256>>>();
    lstm_mma_kernel<1><<<((NN_ + 63) / 64) * 2, 256, SMEM_SZ>>>(
        node_c, bih_n, bhh_n, nullptr, nullptr, node_graph, n_out, h_n, c_n, NN_);

    // 4) graph LSTM
    graph_lstm_kernel<<<B_, 256>>>(
        g_repr, graph_h, graph_c,
        Wih_u, Whh_u, bih_u, bhh_u,
        u_out, h_u, c_u);
}

// round 16
// speedup vs baseline: 1.4273x; 1.4273x over previous
#include <cuda_runtime.h>
#include <cuda_fp16.h>
#include <math.h>
#include <stdint.h>

#define E_ 400000
#define NN_ 50000
#define B_ 50

// ---------------- device scratch (no allocs allowed) ----------------
__device__ float g_mail[NN_ * 64];
__device__ float g_ecomb[B_ * 64];
__device__ float g_ncomb[B_ * 64];
__device__ float g_gbias_e[B_ * 256];
__device__ float g_gbias_n[B_ * 256];
// fp16 weights, rows PERMUTED to d-major (r = d*4+gate), stored PRE-SWIZZLED
// (SW128) per (half, chunk) 16KB block for bulk copy.
__device__ __align__(128) __half g_W_e[256 * 256];   // 8 blocks of 8192
__device__ __align__(128) __half g_W_n[256 * 192];   // 6 blocks of 8192
// fp16 activations (single rounding)
__device__ __align__(16) __half g_nf[NN_ * 64];
__device__ __align__(16) __half g_nh[NN_ * 64];
__device__ __align__(16) __half g_ml[NN_ * 64];
__device__ __align__(16) __half g_ef[E_ * 64];
__device__ __align__(16) __half g_eh[E_ * 64];

// ---------------- smem layout (bytes) ----------------
#define OFF_BIAS 0                     // 128 f32 (permuted bias, this half)
#define OFF_RSUM 512                   // 64 f32
#define OFF_GB   768                   // 2 x 128 f32 (permuted gbias)
#define OFF_MBAR 1792                  // 2 mbarriers
#define OFF_A    3712                  // A[buf]: 64*144 = 9216 each
#define ABUF(buf) (OFF_A + (buf) * 9216)
#define OFF_B    22528                 // B[buf]: 16384 each (1KB aligned)
#define BBUF(buf) (OFF_B + (buf) * 16384)
#define OFF_GATES 3712                 // overlay after GEMM: 64 x 132 f32 = 33792
#define SMEM_SZ  55296
#define BCHUNK_BYTES 16384

// ---------------- PTX helpers (baseline PTX only) ----------------
__device__ __forceinline__ uint32_t smem_u32(const void* p) {
    uint32_t a;
    asm("{ .reg .u64 t; cvta.to.shared.u64 t, %1; cvt.u32.u64 %0, t; }" : "=r"(a) : "l"(p));
    return a;
}
#define CP_ASYNC16(dst, src) \
    asm volatile("cp.async.ca.shared.global [%0], [%1], 16;" :: "r"(dst), "l"(src))
#define CP_COMMIT() asm volatile("cp.async.commit_group;" ::: "memory")
#define CP_WAIT0()  asm volatile("cp.async.wait_group 0;" ::: "memory")

#define MBARRIER_INIT(addr, cnt) \
    asm volatile("mbarrier.init.shared.b64 [%0], %1;" :: "r"((uint32_t)(addr)), "r"((uint32_t)(cnt)) : "memory")
#define MBARRIER_EXPECT_TX(addr, bytes) \
    asm volatile("mbarrier.arrive.expect_tx.shared.b64 _, [%0], %1;" :: "r"((uint32_t)(addr)), "r"((uint32_t)(bytes)) : "memory")
#define CP_BULK(dst, src, sz, mbar) \
    asm volatile("cp.async.bulk.shared::cta.global.mbarrier::complete_tx::bytes [%0], [%1], %2, [%3];" \
        :: "r"((uint32_t)(dst)), "l"(src), "r"((uint32_t)(sz)), "r"((uint32_t)(mbar)) : "memory")
#define MBAR_WAIT(addr, parity) do { \
    uint32_t _m = (uint32_t)(addr); uint32_t _p = (uint32_t)(parity); uint32_t _d; \
    asm volatile("{ .reg .pred p; mbarrier.try_wait.parity.shared.b64 p, [%1], %2; selp.b32 %0, 1, 0, p; }" \
        : "=r"(_d) : "r"(_m), "r"(_p) : "memory"); \
    if (!_d) { \
        asm volatile("{ .reg .pred P1; WL_%=: mbarrier.try_wait.parity.shared.b64 P1, [%0], %1; @P1 bra.uni WD_%=; bra.uni WL_%=; WD_%=: }" \
            :: "r"(_m), "r"(_p) : "memory"); \
    } } while (0)

__device__ __forceinline__ void ldsm4(uint32_t* r, uint32_t a) {
    asm volatile("ldmatrix.sync.aligned.m8n8.x4.shared.b16 {%0,%1,%2,%3}, [%4];"
        : "=r"(r[0]), "=r"(r[1]), "=r"(r[2]), "=r"(r[3]) : "r"(a));
}
__device__ __forceinline__ void mma16816(float* d, const uint32_t* a, uint32_t b0, uint32_t b1) {
    asm volatile("mma.sync.aligned.m16n8k16.row.col.f32.f16.f16.f32 "
        "{%0,%1,%2,%3},{%4,%5,%6,%7},{%8,%9},{%0,%1,%2,%3};"
        : "+f"(d[0]), "+f"(d[1]), "+f"(d[2]), "+f"(d[3])
        : "r"(a[0]), "r"(a[1]), "r"(a[2]), "r"(a[3]), "r"(b0), "r"(b1));
}

// ---------------- math helpers ----------------
__device__ __forceinline__ float sigm(float x) { return 1.0f / (1.0f + __expf(-x)); }
__device__ __forceinline__ float tanh_(float x) {
    return __fdividef(2.0f, 1.0f + __expf(-2.0f * x)) - 1.0f;
}

// ---------------- staging ----------------
// A chunk: 64 rows x 64 k fp16, padded rows. 2 cp.async per thread.
template <int MODE>
__device__ __forceinline__ void issue_A(uint32_t smb, int oa,
    int s, int m0, int Mrows, int tid,
    const int* __restrict__ srcI, const int* __restrict__ dstI)
{
    #pragma unroll
    for (int t = 0; t < 2; ++t) {
        int idx = tid + t * 256;
        int rl = idx >> 3, q = idx & 7;
        int grow = m0 + rl;
        if (grow >= Mrows) grow = Mrows - 1;
        const __half* base;
        size_t ridx;
        if (MODE == 0) {
            if (s == 0)      { base = g_ef; ridx = (size_t)grow; }
            else if (s == 1) { base = g_nf; ridx = (size_t)srcI[grow]; }
            else if (s == 2) { base = g_nf; ridx = (size_t)dstI[grow]; }
            else             { base = g_eh; ridx = (size_t)grow; }
        } else {
            if (s == 0)      base = g_nf;
            else if (s == 1) base = g_ml;
            else             base = g_nh;
            ridx = (size_t)grow;
        }
        CP_ASYNC16(smb + oa + rl * 144 + q * 16,
                   (const char*)(base + ridx * 64 + q * 8));
    }
}

// single-pass fp16 mma over one K=64 chunk; warp tile 32 rows x 32 cols
__device__ __forceinline__ void compute64(uint32_t smb, int aB, int bB,
                                          uint32_t aoff, uint32_t bbase,
                                          uint32_t bcx, uint32_t xterm,
                                          float (&acc)[2][4][4])
{
    #pragma unroll
    for (int kt = 0; kt < 4; ++kt) {
        const uint32_t bco = (bcx + kt * 32) ^ xterm;
        uint32_t b4[2][4];
        #pragma unroll
        for (int g = 0; g < 2; ++g) ldsm4(b4[g], smb + bB + bbase + g * 2048 + bco);
        #pragma unroll
        for (int mt = 0; mt < 2; ++mt) {
            uint32_t a[4];
            ldsm4(a, smb + aB + aoff + mt * 2304 + kt * 32);
            #pragma unroll
            for (int g = 0; g < 2; ++g) {
                mma16816(acc[mt][2 * g],     a, b4[g][0], b4[g][2]);
                mma16816(acc[mt][2 * g + 1], a, b4[g][1], b4[g][3]);
            }
        }
    }
}

// MODE 0: edge (K=256), MODE 1: node (K=192).
// CTA = 64 rows x 128 permuted gate-cols (half h covers d in [h*32, h*32+32)).
template <int MODE>
__global__ void __launch_bounds__(256, 3)
lstm_mma_kernel(const float* __restrict__ c_in,
                const float* __restrict__ bih,
                const float* __restrict__ bhh,
                const int* __restrict__ srcI,
                const int* __restrict__ dstI,
                const int* __restrict__ rgraph,
                float* __restrict__ out_r,
                float* __restrict__ out_h,
                float* __restrict__ out_c,
                int Mrows)
{
    constexpr int KTOT = (MODE == 0) ? 256 : 192;
    constexpr int NC = KTOT / 64;
    extern __shared__ char sm[];
    const uint32_t smb = smem_u32(sm);
    float* bias_s  = (float*)(sm + OFF_BIAS);
    float* rsum    = (float*)(sm + OFF_RSUM);
    float* gb_s    = (float*)(sm + OFF_GB);
    float* gates_s = (float*)(sm + OFF_GATES);

    const int tid = threadIdx.x;
    const int lane = tid & 31;
    const int wid = tid >> 5;
    const int m0 = (blockIdx.x >> 1) * 64;
    const int h = blockIdx.x & 1;
    const __half* W = ((MODE == 0) ? g_W_e : g_W_n) + (size_t)h * NC * 8192;
    const float* gbias = (MODE == 0) ? g_gbias_e : g_gbias_n;

    if (tid == 0) {
        MBARRIER_INIT(smb + OFF_MBAR, 1);
        MBARRIER_INIT(smb + OFF_MBAR + 8, 1);
    }
    // permuted bias for this half: bias_s[dl*4+gate]
    if (tid < 128) {
        int gate = tid & 3, dl = tid >> 2;
        bias_s[tid] = bih[gate * 64 + h * 32 + dl] + bhh[gate * 64 + h * 32 + dl];
    }
    if (tid < 64) rsum[tid] = 0.f;

    const int gfirst = rgraph[m0];
    int mlast = (m0 + 63 < Mrows) ? (m0 + 63) : (Mrows - 1);
    const int glast = rgraph[mlast];
    {   // permuted gbias: gb_s[sel*128 + dl*4+gate]
        int sel = tid >> 7, t2 = tid & 127;
        int gate = t2 & 3, dl = t2 >> 2;
        gb_s[tid] = gbias[(size_t)(sel ? glast : gfirst) * 256 + gate * 64 + h * 32 + dl];
    }
    __syncthreads();

    // prologue: chunk 0
    issue_A<MODE>(smb, ABUF(0), 0, m0, Mrows, tid, srcI, dstI);
    CP_COMMIT();
    if (tid == 0) {
        MBARRIER_EXPECT_TX(smb + OFF_MBAR, BCHUNK_BYTES);
        CP_BULK(smb + BBUF(0), (const char*)W, BCHUNK_BYTES, smb + OFF_MBAR);
    }
    CP_WAIT0();
    MBAR_WAIT(smb + OFF_MBAR, 0);
    __syncthreads();

    float acc[2][4][4];
    #pragma unroll
    for (int i = 0; i < 2; ++i)
        #pragma unroll
        for (int j = 0; j < 4; ++j)
            #pragma unroll
            for (int k = 0; k < 4; ++k) acc[i][j][k] = 0.f;

    const int wm = wid & 1, wn = wid >> 1;    // 2 x 4 warp grid; warp tile 32x32
    const uint32_t aoff  = (uint32_t)((wm * 32 + (lane & 15)) * 144 + (lane >> 4) * 16);
    const uint32_t bbase = (uint32_t)((wn * 32 + (lane & 15)) * 128);
    const uint32_t bcx   = (uint32_t)((lane >> 4) * 16);
    const uint32_t xterm = (uint32_t)((lane & 7) << 4);

    #pragma unroll 1
    for (int c = 0; c < NC; ++c) {
        const int cur = c & 1, nxt = cur ^ 1;
        const bool have_next = (c + 1 < NC);
        if (have_next) {
            issue_A<MODE>(smb, ABUF(nxt), c + 1, m0, Mrows, tid, srcI, dstI);
            CP_COMMIT();
            if (tid == 0) {
                MBARRIER_EXPECT_TX(smb + OFF_MBAR + 8 * nxt, BCHUNK_BYTES);
                CP_BULK(smb + BBUF(nxt),
                        (const char*)W + (size_t)(c + 1) * BCHUNK_BYTES,
                        BCHUNK_BYTES, smb + OFF_MBAR + 8 * nxt);
            }
        }
        compute64(smb, ABUF(cur), BBUF(cur), aoff, bbase, bcx, xterm, acc);
        if (have_next) {
            CP_WAIT0();
            MBAR_WAIT(smb + OFF_MBAR + 8 * nxt, ((c + 1) >> 1) & 1);
        }
        __syncthreads();
    }

    // ---- acc -> gates_s[64][132] (overlays A/B smem) ----
    #pragma unroll
    for (int mt = 0; mt < 2; ++mt) {
        int r0 = wm * 32 + mt * 16 + (lane >> 2);
        #pragma unroll
        for (int nt = 0; nt < 4; ++nt) {
            int nc = wn * 32 + nt * 8 + (lane & 3) * 2;
            *(float2*)&gates_s[r0 * 132 + nc]       = make_float2(acc[mt][nt][0], acc[mt][nt][1]);
            *(float2*)&gates_s[(r0 + 8) * 132 + nc] = make_float2(acc[mt][nt][2], acc[mt][nt][3]);
        }
    }
    __syncthreads();

    // ---- fused LSTM pointwise + mailbox scatter + per-graph sums ----
    const int dl = tid & 31;
    const int d = h * 32 + dl;
    // pre-combined bias+gbias (two graph variants) as float4
    float4 bb = *(float4*)&bias_s[dl * 4];
    float4 g0 = *(float4*)&gb_s[dl * 4];
    float4 g1 = *(float4*)&gb_s[128 + dl * 4];
    float4 bf0 = make_float4(bb.x + g0.x, bb.y + g0.y, bb.z + g0.z, bb.w + g0.w);
    float4 bf1 = make_float4(bb.x + g1.x, bb.y + g1.y, bb.z + g1.z, bb.w + g1.w);

    float a0 = 0.f, a1 = 0.f;
    #pragma unroll 2
    for (int it = 0; it < 8; ++it) {
        int ml = it * 8 + (tid >> 5);
        int grow = m0 + ml;
        if (grow < Mrows) {
            bool first = (rgraph[grow] == gfirst);
            float4 bv = first ? bf0 : bf1;
            float4 gv = *(float4*)&gates_s[ml * 132 + dl * 4];   // i,f,g,o
            float gi = gv.x + bv.x;
            float gf = gv.y + bv.y;
            float gg = gv.z + bv.z;
            float go = gv.w + bv.w;
            float c2 = sigm(gf) * c_in[(size_t)grow * 64 + d] + sigm(gi) * tanh_(gg);
            float hh = sigm(go) * tanh_(c2);
            float r = fmaxf(hh, 0.f);
            out_r[(size_t)grow * 64 + d] = r;
            out_h[(size_t)grow * 64 + d] = hh;
            out_c[(size_t)grow * 64 + d] = c2;
            if (MODE == 0) atomicAdd(&g_mail[(size_t)dstI[grow] * 64 + d], r);
            if (first) a0 += r; else a1 += r;
        }
    }
    atomicAdd(&rsum[dl], a0);
    atomicAdd(&rsum[32 + dl], a1);
    __syncthreads();
    float* comb = (MODE == 0) ? g_ecomb : g_ncomb;
    if (tid < 32) atomicAdd(&comb[(size_t)gfirst * 64 + h * 32 + tid], rsum[tid]);
    else if (tid < 64 && glast != gfirst)
        atomicAdd(&comb[(size_t)glast * 64 + h * 32 + (tid - 32)], rsum[32 + tid - 32]);
}

// ---------------- prep kernels ----------------
__device__ __forceinline__ uint2 cvt4(float4 v) {
    __half2 h01 = __floats2half2_rn(v.x, v.y);
    __half2 h23 = __floats2half2_rn(v.z, v.w);
    uint2 r;
    r.x = *(uint32_t*)&h01;
    r.y = *(uint32_t*)&h23;
    return r;
}

// fused: convert ef/eh/nf/nh to fp16 (vectorized x8) + zero scratch
__global__ void prep_kernel(const float* __restrict__ ef, const float* __restrict__ eh,
                            const float* __restrict__ nf, const float* __restrict__ nh)
{
    size_t i8 = ((size_t)blockIdx.x * 256 + threadIdx.x) * 8;
    if (i8 < (size_t)E_ * 64) {
        uint4 o;
        uint2 a = cvt4(*(const float4*)(ef + i8));
        uint2 b = cvt4(*(const float4*)(ef + i8 + 4));
        o.x = a.x; o.y = a.y; o.z = b.x; o.w = b.y;
        *(uint4*)(g_ef + i8) = o;
        a = cvt4(*(const float4*)(eh + i8));
        b = cvt4(*(const float4*)(eh + i8 + 4));
        o.x = a.x; o.y = a.y; o.z = b.x; o.w = b.y;
        *(uint4*)(g_eh + i8) = o;
    }
    if (i8 < (size_t)NN_ * 64) {
        uint4 o;
        uint2 a = cvt4(*(const float4*)(nf + i8));
        uint2 b = cvt4(*(const float4*)(nf + i8 + 4));
        o.x = a.x; o.y = a.y; o.z = b.x; o.w = b.y;
        *(uint4*)(g_nf + i8) = o;
        a = cvt4(*(const float4*)(nh + i8));
        b = cvt4(*(const float4*)(nh + i8 + 4));
        o.x = a.x; o.y = a.y; o.z = b.x; o.w = b.y;
        *(uint4*)(g_nh + i8) = o;
        *(float4*)(g_mail + i8) = make_float4(0.f, 0.f, 0.f, 0.f);
        *(float4*)(g_mail + i8 + 4) = make_float4(0.f, 0.f, 0.f, 0.f);
    }
    if (i8 < B_ * 64) {
        *(float4*)(g_ecomb + i8) = make_float4(0.f, 0.f, 0.f, 0.f);
        *(float4*)(g_ecomb + i8 + 4) = make_float4(0.f, 0.f, 0.f, 0.f);
        *(float4*)(g_ncomb + i8) = make_float4(0.f, 0.f, 0.f, 0.f);
        *(float4*)(g_ncomb + i8 + 4) = make_float4(0.f, 0.f, 0.f, 0.f);
    }
}

// W -> fp16, rows permuted to d-major (r = d*4+gate), pre-swizzled per
// (half, chunk) 16KB block: block = h*NC + c.
__global__ void splitw_kernel(const float* __restrict__ Wih_e, const float* __restrict__ Whh_e,
                              const float* __restrict__ Wih_n, const float* __restrict__ Whh_n)
{
    int i = blockIdx.x * 256 + threadIdx.x;
    if (i < 256 * 256) {
        int go = i >> 8, k = i & 255;
        float v = (k < 192) ? Wih_e[go * 256 + k] : Whh_e[go * 64 + (k - 192)];
        int gate = go >> 6, d = go & 63;
        int r = d * 4 + gate;
        int hh = r >> 7, rr = r & 127;
        int c = k >> 6, kl = k & 63;
        uint32_t off = (uint32_t)(rr * 128 + kl * 2);
        uint32_t sw = off ^ ((off >> 3) & 0x70);
        g_W_e[(hh * 4 + c) * 8192 + (sw >> 1)] = __float2half_rn(v);
    }
    if (i < 256 * 192) {
        int go = i / 192, k = i - go * 192;
        float v = (k < 128) ? Wih_n[go * 192 + k] : Whh_n[go * 64 + (k - 128)];
        int gate = go >> 6, d = go & 63;
        int r = d * 4 + gate;
        int hh = r >> 7, rr = r & 127;
        int c = k >> 6, kl = k & 63;
        uint32_t off = (uint32_t)(rr * 128 + kl * 2);
        uint32_t sw = off ^ ((off >> 3) & 0x70);
        g_W_n[(hh * 3 + c) * 8192 + (sw >> 1)] = __float2half_rn(v);
    }
}

// per-graph gate bias: grepr @ Wseg (f32, exact; unpermuted — kernel permutes on load)
__global__ void gbias_kernel(const float* __restrict__ grepr,
                             const float* __restrict__ Wih_e,
                             const float* __restrict__ Wih_n)
{
    __shared__ float gsh[64];
    const int b = blockIdx.x, tid = threadIdx.x;
    if (tid < 64) gsh[tid] = grepr[b * 64 + tid];
    __syncthreads();
    float ae = 0.f, an = 0.f;
    #pragma unroll 8
    for (int k = 0; k < 64; ++k) {
        ae += gsh[k] * Wih_e[tid * 256 + 192 + k];
        an += gsh[k] * Wih_n[tid * 192 + 128 + k];
    }
    g_gbias_e[b * 256 + tid] = ae;
    g_gbias_n[b * 256 + tid] = an;
}

__global__ void split_mail_kernel()
{
    size_t i8 = ((size_t)blockIdx.x * 256 + threadIdx.x) * 8;
    if (i8 < (size_t)NN_ * 64) {
        uint4 o;
        uint2 a = cvt4(*(const float4*)(g_mail + i8));
        uint2 b = cvt4(*(const float4*)(g_mail + i8 + 4));
        o.x = a.x; o.y = a.y; o.z = b.x; o.w = b.y;
        *(uint4*)(g_ml + i8) = o;
    }
}

// ---------------- graph-level LSTM (B=50) ----------------
__global__ void graph_lstm_kernel(
    const float* __restrict__ grepr,
    const float* __restrict__ h_in,
    const float* __restrict__ c_in,
    const float* __restrict__ Wih,
    const float* __restrict__ Whh,
    const float* __restrict__ bih,
    const float* __restrict__ bhh,
    float* __restrict__ out_r,
    float* __restrict__ out_h,
    float* __restrict__ out_c)
{
    __shared__ float xu[256];
    __shared__ float gs[256];
    const int b = blockIdx.x;
    const int tid = threadIdx.x;

    if (tid < 64)       xu[tid] = g_ncomb[b * 64 + tid];
    else if (tid < 128) xu[tid] = g_ecomb[b * 64 + (tid - 64)];
    else if (tid < 192) xu[tid] = grepr[b * 64 + (tid - 128)];
    else                xu[tid] = h_in[b * 64 + (tid - 192)];
    __syncthreads();

    float a = bih[tid] + bhh[tid];
    const float* wih_row = Wih + (size_t)tid * 192;
    #pragma unroll 8
    for (int k4 = 0; k4 < 48; ++k4) {
        float4 w = *(const float4*)&wih_row[k4 * 4];
        a += w.x * xu[k4 * 4] + w.y * xu[k4 * 4 + 1] + w.z * xu[k4 * 4 + 2] + w.w * xu[k4 * 4 + 3];
    }
    const float* whh_row = Whh + (size_t)tid * 64;
    #pragma unroll 8
    for (int k4 = 0; k4 < 16; ++k4) {
        float4 w = *(const float4*)&whh_row[k4 * 4];
        a += w.x * xu[192 + k4 * 4] + w.y * xu[192 + k4 * 4 + 1]
           + w.z * xu[192 + k4 * 4 + 2] + w.w * xu[192 + k4 * 4 + 3];
    }
    gs[tid] = a;
    __syncthreads();

    if (tid < 64) {
        float gi = gs[tid], gf = gs[64 + tid], gg = gs[128 + tid], go = gs[192 + tid];
        float c2 = sigm(gf) * c_in[b * 64 + tid] + sigm(gi) * tanh_(gg);
        float h = sigm(go) * tanh_(c2);
        out_r[b * 64 + tid] = fmaxf(h, 0.f);
        out_h[b * 64 + tid] = h;
        out_c[b * 64 + tid] = c2;
    }
}

extern "C" void kernel_launch(void* const* d_in, const int* in_sizes, int n_in,
                              void* d_out, int out_size)
{
    const float* edge_feat  = (const float*)d_in[0];
    const float* node_feat  = (const float*)d_in[1];
    const float* g_repr     = (const float*)d_in[2];
    const float* edge_h     = (const float*)d_in[3];
    const float* edge_c     = (const float*)d_in[4];
    const float* node_h     = (const float*)d_in[5];
    const float* node_c     = (const float*)d_in[6];
    const float* graph_h    = (const float*)d_in[7];
    const float* graph_c    = (const float*)d_in[8];
    const float* Wih_e      = (const float*)d_in[9];
    const float* Whh_e      = (const float*)d_in[10];
    const float* bih_e      = (const float*)d_in[11];
    const float* bhh_e      = (const float*)d_in[12];
    const float* Wih_n      = (const float*)d_in[13];
    const float* Whh_n      = (const float*)d_in[14];
    const float* bih_n      = (const float*)d_in[15];
    const float* bhh_n      = (const float*)d_in[16];
    const float* Wih_u      = (const float*)d_in[17];
    const float* Whh_u      = (const float*)d_in[18];
    const float* bih_u      = (const float*)d_in[19];
    const float* bhh_u      = (const float*)d_in[20];
    const int*   src        = (const int*)d_in[21];
    const int*   dst        = (const int*)d_in[22];
    const int*   edge_graph = (const int*)d_in[23];
    const int*   node_graph = (const int*)d_in[24];

    float* out = (float*)d_out;
    const size_t ED = (size_t)E_ * 64;
    const size_t ND = (size_t)NN_ * 64;
    const size_t BD = (size_t)B_ * 64;
    float* e_out = out;
    float* h_e   = out + ED;
    float* c_e   = out + 2 * ED;
    float* n_out = out + 3 * ED;
    float* h_n   = n_out + ND;
    float* c_n   = n_out + 2 * ND;
    float* u_out = n_out + 3 * ND;
    float* h_u   = u_out + BD;
    float* c_u   = u_out + 2 * BD;

    cudaFuncSetAttribute(lstm_mma_kernel<0>, cudaFuncAttributeMaxDynamicSharedMemorySize, SMEM_SZ);
    cudaFuncSetAttribute(lstm_mma_kernel<1>, cudaFuncAttributeMaxDynamicSharedMemorySize, SMEM_SZ);

    // 1) prep
    prep_kernel<<<(int)(((size_t)E_ * 64 / 8 + 255) / 256), 256>>>(edge_feat, edge_h, node_feat, node_h);
    splitw_kernel<<<256, 256>>>(Wih_e, Whh_e, Wih_n, Whh_n);
    gbias_kernel<<<B_, 256>>>(g_repr, Wih_e, Wih_n);

    // 2) edge LSTM (half-gate CTAs, 3 CTA/SM, smem epilogue) + mailbox + e_comb
    lstm_mma_kernel<0><<<(E_ / 64) * 2, 256, SMEM_SZ>>>(
        edge_c, bih_e, bhh_e, src, dst, edge_graph, e_out, h_e, c_e, E_);

    // 3) convert mail, then node LSTM + n_comb
    split_mail_kernel<<<(NN_ * 64 / 8 + 255) / 256, 256>>>();
    lstm_mma_kernel<1><<<((NN_ + 63) / 64) * 2, 256, SMEM_SZ>>>(
        node_c, bih_n, bhh_n, nullptr, nullptr, node_graph, n_out, h_n, c_n, NN_);

    // 4) graph LSTM
    graph_lstm_kernel<<<B_, 256>>>(
        g_repr, graph_h, graph_c,
        Wih_u, Whh_u, bih_u, bhh_u,
        u_out, h_u, c_u);
}

// round 17
// speedup vs baseline: 1.4881x; 1.0426x over previous
#include <cuda_runtime.h>
#include <cuda_fp16.h>
#include <math.h>
#include <stdint.h>

#define E_ 400000
#define NN_ 50000
#define B_ 50

// ---------------- device scratch (no allocs allowed) ----------------
__device__ float g_mail[NN_ * 64];
__device__ float g_ecomb[B_ * 64];
__device__ float g_ncomb[B_ * 64];
__device__ float g_gbias_e[B_ * 256];
__device__ float g_gbias_n[B_ * 256];
// fp16 weights, rows PERMUTED to d-major (r = d*4+gate), stored PRE-SWIZZLED
// (SW128) per (half, chunk) 16KB block for bulk copy.
__device__ __align__(128) __half g_W_e[256 * 128];   // edge: [ef|eh], 4 blocks of 8192
__device__ __align__(128) __half g_W_n[256 * 192];   // node: 6 blocks of 8192
__device__ __align__(128) __half g_Wpre[512 * 64];   // [G1|G2] pre-GEMM W, 4 blocks of 8192
// per-node precomputed gate partials: [node][G1 perm 256 | G2 perm 256], fp16
__device__ __align__(16) __half g_G[(size_t)NN_ * 512];
// fp16 activations (single rounding)
__device__ __align__(16) __half g_nf[NN_ * 64];
__device__ __align__(16) __half g_nh[NN_ * 64];
__device__ __align__(16) __half g_ml[NN_ * 64];
__device__ __align__(16) __half g_ef[E_ * 64];
__device__ __align__(16) __half g_eh[E_ * 64];

// ---------------- smem layout (bytes) ----------------
#define OFF_BIAS 0                     // 128 f32 (permuted bias, this half)
#define OFF_RSUM 512                   // 64 f32
#define OFF_GB   768                   // 2 x 128 f32 (permuted gbias)
#define OFF_MBAR 1792                  // 2 mbarriers
#define OFF_A    3712                  // A[buf]: 64*144 = 9216 each
#define ABUF(buf) (OFF_A + (buf) * 9216)
#define OFF_B    22528                 // B[buf]: 16384 each (1KB aligned)
#define BBUF(buf) (OFF_B + (buf) * 16384)
#define OFF_GATES 3712                 // overlay after GEMM: 64 x 132 f32 = 33792
#define SMEM_SZ  55296
#define BCHUNK_BYTES 16384

// ---------------- PTX helpers (baseline PTX only) ----------------
__device__ __forceinline__ uint32_t smem_u32(const void* p) {
    uint32_t a;
    asm("{ .reg .u64 t; cvta.to.shared.u64 t, %1; cvt.u32.u64 %0, t; }" : "=r"(a) : "l"(p));
    return a;
}
#define CP_ASYNC16(dst, src) \
    asm volatile("cp.async.ca.shared.global [%0], [%1], 16;" :: "r"(dst), "l"(src))
#define CP_COMMIT() asm volatile("cp.async.commit_group;" ::: "memory")
#define CP_WAIT0()  asm volatile("cp.async.wait_group 0;" ::: "memory")

#define MBARRIER_INIT(addr, cnt) \
    asm volatile("mbarrier.init.shared.b64 [%0], %1;" :: "r"((uint32_t)(addr)), "r"((uint32_t)(cnt)) : "memory")
#define MBARRIER_EXPECT_TX(addr, bytes) \
    asm volatile("mbarrier.arrive.expect_tx.shared.b64 _, [%0], %1;" :: "r"((uint32_t)(addr)), "r"((uint32_t)(bytes)) : "memory")
#define CP_BULK(dst, src, sz, mbar) \
    asm volatile("cp.async.bulk.shared::cta.global.mbarrier::complete_tx::bytes [%0], [%1], %2, [%3];" \
        :: "r"((uint32_t)(dst)), "l"(src), "r"((uint32_t)(sz)), "r"((uint32_t)(mbar)) : "memory")
#define MBAR_WAIT(addr, parity) do { \
    uint32_t _m = (uint32_t)(addr); uint32_t _p = (uint32_t)(parity); uint32_t _d; \
    asm volatile("{ .reg .pred p; mbarrier.try_wait.parity.shared.b64 p, [%1], %2; selp.b32 %0, 1, 0, p; }" \
        : "=r"(_d) : "r"(_m), "r"(_p) : "memory"); \
    if (!_d) { \
        asm volatile("{ .reg .pred P1; WL_%=: mbarrier.try_wait.parity.shared.b64 P1, [%0], %1; @P1 bra.uni WD_%=; bra.uni WL_%=; WD_%=: }" \
            :: "r"(_m), "r"(_p) : "memory"); \
    } } while (0)

__device__ __forceinline__ void ldsm4(uint32_t* r, uint32_t a) {
    asm volatile("ldmatrix.sync.aligned.m8n8.x4.shared.b16 {%0,%1,%2,%3}, [%4];"
        : "=r"(r[0]), "=r"(r[1]), "=r"(r[2]), "=r"(r[3]) : "r"(a));
}
__device__ __forceinline__ void mma16816(float* d, const uint32_t* a, uint32_t b0, uint32_t b1) {
    asm volatile("mma.sync.aligned.m16n8k16.row.col.f32.f16.f16.f32 "
        "{%0,%1,%2,%3},{%4,%5,%6,%7},{%8,%9},{%0,%1,%2,%3};"
        : "+f"(d[0]), "+f"(d[1]), "+f"(d[2]), "+f"(d[3])
        : "r"(a[0]), "r"(a[1]), "r"(a[2]), "r"(a[3]), "r"(b0), "r"(b1));
}

// ---------------- math helpers ----------------
__device__ __forceinline__ float sigm(float x) { return 1.0f / (1.0f + __expf(-x)); }
__device__ __forceinline__ float tanh_(float x) {
    return __fdividef(2.0f, 1.0f + __expf(-2.0f * x)) - 1.0f;
}

// ---------------- staging ----------------
// A chunk: 64 rows x 64 k fp16, padded rows. 2 cp.async per thread.
template <int MODE>
__device__ __forceinline__ void issue_A(uint32_t smb, int oa,
    int s, int m0, int Mrows, int tid)
{
    #pragma unroll
    for (int t = 0; t < 2; ++t) {
        int idx = tid + t * 256;
        int rl = idx >> 3, q = idx & 7;
        int grow = m0 + rl;
        if (grow >= Mrows) grow = Mrows - 1;
        const __half* base;
        if (MODE == 0) {
            base = (s == 0) ? g_ef : g_eh;
        } else {
            if (s == 0)      base = g_nf;
            else if (s == 1) base = g_ml;
            else             base = g_nh;
        }
        CP_ASYNC16(smb + oa + rl * 144 + q * 16,
                   (const char*)(base + (size_t)grow * 64 + q * 8));
    }
}

// single-pass fp16 mma over one K=64 chunk; warp tile 32 rows x 32 cols
__device__ __forceinline__ void compute64(uint32_t smb, int aB, int bB,
                                          uint32_t aoff, uint32_t bbase,
                                          uint32_t bcx, uint32_t xterm,
                                          float (&acc)[2][4][4])
{
    #pragma unroll
    for (int kt = 0; kt < 4; ++kt) {
        const uint32_t bco = (bcx + kt * 32) ^ xterm;
        uint32_t b4[2][4];
        #pragma unroll
        for (int g = 0; g < 2; ++g) ldsm4(b4[g], smb + bB + bbase + g * 2048 + bco);
        #pragma unroll
        for (int mt = 0; mt < 2; ++mt) {
            uint32_t a[4];
            ldsm4(a, smb + aB + aoff + mt * 2304 + kt * 32);
            #pragma unroll
            for (int g = 0; g < 2; ++g) {
                mma16816(acc[mt][2 * g],     a, b4[g][0], b4[g][2]);
                mma16816(acc[mt][2 * g + 1], a, b4[g][1], b4[g][3]);
            }
        }
    }
}

// MODE 0: edge (K=128: ef | eh; nf[src]/nf[dst] folded via g_G), MODE 1: node (K=192).
// CTA = 64 rows x 128 permuted gate-cols (half h covers d in [h*32, h*32+32)).
template <int MODE>
__global__ void __launch_bounds__(256, 3)
lstm_mma_kernel(const float* __restrict__ c_in,
                const float* __restrict__ bih,
                const float* __restrict__ bhh,
                const int* __restrict__ srcI,
                const int* __restrict__ dstI,
                const int* __restrict__ rgraph,
                float* __restrict__ out_r,
                float* __restrict__ out_h,
                float* __restrict__ out_c,
                int Mrows)
{
    constexpr int KTOT = (MODE == 0) ? 128 : 192;
    constexpr int NC = KTOT / 64;
    extern __shared__ char sm[];
    const uint32_t smb = smem_u32(sm);
    float* bias_s  = (float*)(sm + OFF_BIAS);
    float* rsum    = (float*)(sm + OFF_RSUM);
    float* gb_s    = (float*)(sm + OFF_GB);
    float* gates_s = (float*)(sm + OFF_GATES);

    const int tid = threadIdx.x;
    const int lane = tid & 31;
    const int wid = tid >> 5;
    const int m0 = (blockIdx.x >> 1) * 64;
    const int h = blockIdx.x & 1;
    const __half* W = ((MODE == 0) ? g_W_e : g_W_n) + (size_t)h * NC * 8192;
    const float* gbias = (MODE == 0) ? g_gbias_e : g_gbias_n;

    if (tid == 0) {
        MBARRIER_INIT(smb + OFF_MBAR, 1);
        MBARRIER_INIT(smb + OFF_MBAR + 8, 1);
    }
    // permuted bias for this half: bias_s[dl*4+gate]
    if (tid < 128) {
        int gate = tid & 3, dl = tid >> 2;
        bias_s[tid] = bih[gate * 64 + h * 32 + dl] + bhh[gate * 64 + h * 32 + dl];
    }
    if (tid < 64) rsum[tid] = 0.f;

    const int gfirst = rgraph[m0];
    int mlast = (m0 + 63 < Mrows) ? (m0 + 63) : (Mrows - 1);
    const int glast = rgraph[mlast];
    {   // permuted gbias: gb_s[sel*128 + dl*4+gate]
        int sel = tid >> 7, t2 = tid & 127;
        int gate = t2 & 3, dl = t2 >> 2;
        gb_s[tid] = gbias[(size_t)(sel ? glast : gfirst) * 256 + gate * 64 + h * 32 + dl];
    }
    __syncthreads();

    // prologue: chunk 0
    issue_A<MODE>(smb, ABUF(0), 0, m0, Mrows, tid);
    CP_COMMIT();
    if (tid == 0) {
        MBARRIER_EXPECT_TX(smb + OFF_MBAR, BCHUNK_BYTES);
        CP_BULK(smb + BBUF(0), (const char*)W, BCHUNK_BYTES, smb + OFF_MBAR);
    }
    CP_WAIT0();
    MBAR_WAIT(smb + OFF_MBAR, 0);
    __syncthreads();

    float acc[2][4][4];
    #pragma unroll
    for (int i = 0; i < 2; ++i)
        #pragma unroll
        for (int j = 0; j < 4; ++j)
            #pragma unroll
            for (int k = 0; k < 4; ++k) acc[i][j][k] = 0.f;

    const int wm = wid & 1, wn = wid >> 1;    // 2 x 4 warp grid; warp tile 32x32
    const uint32_t aoff  = (uint32_t)((wm * 32 + (lane & 15)) * 144 + (lane >> 4) * 16);
    const uint32_t bbase = (uint32_t)((wn * 32 + (lane & 15)) * 128);
    const uint32_t bcx   = (uint32_t)((lane >> 4) * 16);
    const uint32_t xterm = (uint32_t)((lane & 7) << 4);

    #pragma unroll 1
    for (int c = 0; c < NC; ++c) {
        const int cur = c & 1, nxt = cur ^ 1;
        const bool have_next = (c + 1 < NC);
        if (have_next) {
            issue_A<MODE>(smb, ABUF(nxt), c + 1, m0, Mrows, tid);
            CP_COMMIT();
            if (tid == 0) {
                MBARRIER_EXPECT_TX(smb + OFF_MBAR + 8 * nxt, BCHUNK_BYTES);
                CP_BULK(smb + BBUF(nxt),
                        (const char*)W + (size_t)(c + 1) * BCHUNK_BYTES,
                        BCHUNK_BYTES, smb + OFF_MBAR + 8 * nxt);
            }
        }
        compute64(smb, ABUF(cur), BBUF(cur), aoff, bbase, bcx, xterm, acc);
        if (have_next) {
            CP_WAIT0();
            MBAR_WAIT(smb + OFF_MBAR + 8 * nxt, ((c + 1) >> 1) & 1);
        }
        __syncthreads();
    }

    // ---- acc -> gates_s[64][132] (overlays A/B smem) ----
    #pragma unroll
    for (int mt = 0; mt < 2; ++mt) {
        int r0 = wm * 32 + mt * 16 + (lane >> 2);
        #pragma unroll
        for (int nt = 0; nt < 4; ++nt) {
            int nc = wn * 32 + nt * 8 + (lane & 3) * 2;
            *(float2*)&gates_s[r0 * 132 + nc]       = make_float2(acc[mt][nt][0], acc[mt][nt][1]);
            *(float2*)&gates_s[(r0 + 8) * 132 + nc] = make_float2(acc[mt][nt][2], acc[mt][nt][3]);
        }
    }
    __syncthreads();

    // ---- fused LSTM pointwise + G gather (edge) + mailbox + per-graph sums ----
    const int dl = tid & 31;
    const int d = h * 32 + dl;
    float4 bb = *(float4*)&bias_s[dl * 4];
    float4 g0 = *(float4*)&gb_s[dl * 4];
    float4 g1 = *(float4*)&gb_s[128 + dl * 4];
    float4 bf0 = make_float4(bb.x + g0.x, bb.y + g0.y, bb.z + g0.z, bb.w + g0.w);
    float4 bf1 = make_float4(bb.x + g1.x, bb.y + g1.y, bb.z + g1.z, bb.w + g1.w);

    float a0 = 0.f, a1 = 0.f;
    #pragma unroll 2
    for (int it = 0; it < 8; ++it) {
        int ml = it * 8 + (tid >> 5);
        int grow = m0 + ml;
        if (grow < Mrows) {
            bool first = (rgraph[grow] == gfirst);
            float4 bv = first ? bf0 : bf1;
            float4 gv = *(float4*)&gates_s[ml * 132 + dl * 4];   // i,f,g,o
            float gi = gv.x + bv.x;
            float gf = gv.y + bv.y;
            float gg = gv.z + bv.z;
            float go = gv.w + bv.w;
            if (MODE == 0) {
                int sr = srcI[grow], dr = dstI[grow];
                uint2 u1 = *(const uint2*)(g_G + (size_t)sr * 512 + h * 128 + dl * 4);
                uint2 u2 = *(const uint2*)(g_G + (size_t)dr * 512 + 256 + h * 128 + dl * 4);
                float2 p1 = __half22float2(*(__half2*)&u1.x);
                float2 p2 = __half22float2(*(__half2*)&u1.y);
                float2 p3 = __half22float2(*(__half2*)&u2.x);
                float2 p4 = __half22float2(*(__half2*)&u2.y);
                gi += p1.x + p3.x;
                gf += p1.y + p3.y;
                gg += p2.x + p4.x;
                go += p2.y + p4.y;
            }
            float c2 = sigm(gf) * c_in[(size_t)grow * 64 + d] + sigm(gi) * tanh_(gg);
            float hh = sigm(go) * tanh_(c2);
            float r = fmaxf(hh, 0.f);
            out_r[(size_t)grow * 64 + d] = r;
            out_h[(size_t)grow * 64 + d] = hh;
            out_c[(size_t)grow * 64 + d] = c2;
            if (MODE == 0) atomicAdd(&g_mail[(size_t)dstI[grow] * 64 + d], r);
            if (first) a0 += r; else a1 += r;
        }
    }
    atomicAdd(&rsum[dl], a0);
    atomicAdd(&rsum[32 + dl], a1);
    __syncthreads();
    float* comb = (MODE == 0) ? g_ecomb : g_ncomb;
    if (tid < 32) atomicAdd(&comb[(size_t)gfirst * 64 + h * 32 + tid], rsum[tid]);
    else if (tid < 64 && glast != gfirst)
        atomicAdd(&comb[(size_t)glast * 64 + h * 32 + (tid - 32)], rsum[32 + tid - 32]);
}

// ---------------- pre-GEMM: G[n] = [nf@W1 | nf@W2] (permuted, fp16) ----------------
// blockIdx = tile*4 + q; q selects 128 of the 512 output cols.
__global__ void __launch_bounds__(256, 3)
gpre_kernel()
{
    extern __shared__ char sm[];
    const uint32_t smb = smem_u32(sm);
    float* gates_s = (float*)(sm + OFF_GATES);
    const int tid = threadIdx.x;
    const int lane = tid & 31;
    const int wid = tid >> 5;
    const int m0 = (blockIdx.x >> 2) * 64;
    const int q = blockIdx.x & 3;

    if (tid == 0) MBARRIER_INIT(smb + OFF_MBAR, 1);
    __syncthreads();

    // stage A: 64 node rows x 64 k from g_nf
    #pragma unroll
    for (int t = 0; t < 2; ++t) {
        int idx = tid + t * 256;
        int rl = idx >> 3, qq = idx & 7;
        int grow = m0 + rl;
        if (grow >= NN_) grow = NN_ - 1;
        CP_ASYNC16(smb + ABUF(0) + rl * 144 + qq * 16,
                   (const char*)(g_nf + (size_t)grow * 64 + qq * 8));
    }
    CP_COMMIT();
    if (tid == 0) {
        MBARRIER_EXPECT_TX(smb + OFF_MBAR, BCHUNK_BYTES);
        CP_BULK(smb + BBUF(0), (const char*)g_Wpre + q * BCHUNK_BYTES,
                BCHUNK_BYTES, smb + OFF_MBAR);
    }
    CP_WAIT0();
    MBAR_WAIT(smb + OFF_MBAR, 0);
    __syncthreads();

    float acc[2][4][4];
    #pragma unroll
    for (int i = 0; i < 2; ++i)
        #pragma unroll
        for (int j = 0; j < 4; ++j)
            #pragma unroll
            for (int k = 0; k < 4; ++k) acc[i][j][k] = 0.f;

    const int wm = wid & 1, wn = wid >> 1;
    const uint32_t aoff  = (uint32_t)((wm * 32 + (lane & 15)) * 144 + (lane >> 4) * 16);
    const uint32_t bbase = (uint32_t)((wn * 32 + (lane & 15)) * 128);
    const uint32_t bcx   = (uint32_t)((lane >> 4) * 16);
    const uint32_t xterm = (uint32_t)((lane & 7) << 4);

    compute64(smb, ABUF(0), BBUF(0), aoff, bbase, bcx, xterm, acc);
    __syncthreads();

    #pragma unroll
    for (int mt = 0; mt < 2; ++mt) {
        int r0 = wm * 32 + mt * 16 + (lane >> 2);
        #pragma unroll
        for (int nt = 0; nt < 4; ++nt) {
            int nc = wn * 32 + nt * 8 + (lane & 3) * 2;
            *(float2*)&gates_s[r0 * 132 + nc]       = make_float2(acc[mt][nt][0], acc[mt][nt][1]);
            *(float2*)&gates_s[(r0 + 8) * 132 + nc] = make_float2(acc[mt][nt][2], acc[mt][nt][3]);
        }
    }
    __syncthreads();

    const int dl = tid & 31;
    #pragma unroll 2
    for (int it = 0; it < 8; ++it) {
        int ml = it * 8 + (tid >> 5);
        int grow = m0 + ml;
        if (grow < NN_) {
            float4 gv = *(float4*)&gates_s[ml * 132 + dl * 4];
            __half2 h01 = __floats2half2_rn(gv.x, gv.y);
            __half2 h23 = __floats2half2_rn(gv.z, gv.w);
            uint2 o;
            o.x = *(uint32_t*)&h01;
            o.y = *(uint32_t*)&h23;
            *(uint2*)(g_G + (size_t)grow * 512 + q * 128 + dl * 4) = o;
        }
    }
}

// ---------------- prep kernels ----------------
__device__ __forceinline__ uint2 cvt4(float4 v) {
    __half2 h01 = __floats2half2_rn(v.x, v.y);
    __half2 h23 = __floats2half2_rn(v.z, v.w);
    uint2 r;
    r.x = *(uint32_t*)&h01;
    r.y = *(uint32_t*)&h23;
    return r;
}

// fused: convert ef/eh/nf/nh to fp16 (vectorized x8) + zero scratch
__global__ void prep_kernel(const float* __restrict__ ef, const float* __restrict__ eh,
                            const float* __restrict__ nf, const float* __restrict__ nh)
{
    size_t i8 = ((size_t)blockIdx.x * 256 + threadIdx.x) * 8;
    if (i8 < (size_t)E_ * 64) {
        uint4 o;
        uint2 a = cvt4(*(const float4*)(ef + i8));
        uint2 b = cvt4(*(const float4*)(ef + i8 + 4));
        o.x = a.x; o.y = a.y; o.z = b.x; o.w = b.y;
        *(uint4*)(g_ef + i8) = o;
        a = cvt4(*(const float4*)(eh + i8));
        b = cvt4(*(const float4*)(eh + i8 + 4));
        o.x = a.x; o.y = a.y; o.z = b.x; o.w = b.y;
        *(uint4*)(g_eh + i8) = o;
    }
    if (i8 < (size_t)NN_ * 64) {
        uint4 o;
        uint2 a = cvt4(*(const float4*)(nf + i8));
        uint2 b = cvt4(*(const float4*)(nf + i8 + 4));
        o.x = a.x; o.y = a.y; o.z = b.x; o.w = b.y;
        *(uint4*)(g_nf + i8) = o;
        a = cvt4(*(const float4*)(nh + i8));
        b = cvt4(*(const float4*)(nh + i8 + 4));
        o.x = a.x; o.y = a.y; o.z = b.x; o.w = b.y;
        *(uint4*)(g_nh + i8) = o;
        *(float4*)(g_mail + i8) = make_float4(0.f, 0.f, 0.f, 0.f);
        *(float4*)(g_mail + i8 + 4) = make_float4(0.f, 0.f, 0.f, 0.f);
    }
    if (i8 < B_ * 64) {
        *(float4*)(g_ecomb + i8) = make_float4(0.f, 0.f, 0.f, 0.f);
        *(float4*)(g_ecomb + i8 + 4) = make_float4(0.f, 0.f, 0.f, 0.f);
        *(float4*)(g_ncomb + i8) = make_float4(0.f, 0.f, 0.f, 0.f);
        *(float4*)(g_ncomb + i8 + 4) = make_float4(0.f, 0.f, 0.f, 0.f);
    }
}

// W -> fp16, rows permuted to d-major (r = d*4+gate), pre-swizzled per 16KB block.
// edge W: [ef|eh] K=128, block (h*2+c); Wpre: [G1|G2] 512 rows x 64k, block q;
// node W unchanged (K=192, block h*3+c).
__global__ void splitw_kernel(const float* __restrict__ Wih_e, const float* __restrict__ Whh_e,
                              const float* __restrict__ Wih_n, const float* __restrict__ Whh_n)
{
    int i = blockIdx.x * 256 + threadIdx.x;
    if (i < 256 * 128) {
        int go = i >> 7, k = i & 127;
        float v = (k < 64) ? Wih_e[go * 256 + k] : Whh_e[go * 64 + (k - 64)];
        int gate = go >> 6, d = go & 63;
        int r = d * 4 + gate;
        int hh = r >> 7, rr = r & 127;
        int c = k >> 6, kl = k & 63;
        uint32_t off = (uint32_t)(rr * 128 + kl * 2);
        uint32_t sw = off ^ ((off >> 3) & 0x70);
        g_W_e[(hh * 2 + c) * 8192 + (sw >> 1)] = __float2half_rn(v);
    }
    if (i < 512 * 64) {
        int rowp = i >> 6, k = i & 63;
        int gsel = rowp >> 8, r = rowp & 255;
        int gate = r & 3, d = r >> 2;
        int go = gate * 64 + d;
        float v = Wih_e[go * 256 + 64 + gsel * 64 + k];
        int q = rowp >> 7, rr = rowp & 127;
        uint32_t off = (uint32_t)(rr * 128 + k * 2);
        uint32_t sw = off ^ ((off >> 3) & 0x70);
        g_Wpre[q * 8192 + (sw >> 1)] = __float2half_rn(v);
    }
    if (i < 256 * 192) {
        int go = i / 192, k = i - go * 192;
        float v = (k < 128) ? Wih_n[go * 192 + k] : Whh_n[go * 64 + (k - 128)];
        int gate = go >> 6, d = go & 63;
        int r = d * 4 + gate;
        int hh = r >> 7, rr = r & 127;
        int c = k >> 6, kl = k & 63;
        uint32_t off = (uint32_t)(rr * 128 + kl * 2);
        uint32_t sw = off ^ ((off >> 3) & 0x70);
        g_W_n[(hh * 3 + c) * 8192 + (sw >> 1)] = __float2half_rn(v);
    }
}

// per-graph gate bias: grepr @ Wseg (f32, exact; unpermuted — kernel permutes on load)
__global__ void gbias_kernel(const float* __restrict__ grepr,
                             const float* __restrict__ Wih_e,
                             const float* __restrict__ Wih_n)
{
    __shared__ float gsh[64];
    const int b = blockIdx.x, tid = threadIdx.x;
    if (tid < 64) gsh[tid] = grepr[b * 64 + tid];
    __syncthreads();
    float ae = 0.f, an = 0.f;
    #pragma unroll 8
    for (int k = 0; k < 64; ++k) {
        ae += gsh[k] * Wih_e[tid * 256 + 192 + k];
        an += gsh[k] * Wih_n[tid * 192 + 128 + k];
    }
    g_gbias_e[b * 256 + tid] = ae;
    g_gbias_n[b * 256 + tid] = an;
}

__global__ void split_mail_kernel()
{
    size_t i8 = ((size_t)blockIdx.x * 256 + threadIdx.x) * 8;
    if (i8 < (size_t)NN_ * 64) {
        uint4 o;
        uint2 a = cvt4(*(const float4*)(g_mail + i8));
        uint2 b = cvt4(*(const float4*)(g_mail + i8 + 4));
        o.x = a.x; o.y = a.y; o.z = b.x; o.w = b.y;
        *(uint4*)(g_ml + i8) = o;
    }
}

// ---------------- graph-level LSTM (B=50) ----------------
__global__ void graph_lstm_kernel(
    const float* __restrict__ grepr,
    const float* __restrict__ h_in,
    const float* __restrict__ c_in,
    const float* __restrict__ Wih,
    const float* __restrict__ Whh,
    const float* __restrict__ bih,
    const float* __restrict__ bhh,
    float* __restrict__ out_r,
    float* __restrict__ out_h,
    float* __restrict__ out_c)
{
    __shared__ float xu[256];
    __shared__ float gs[256];
    const int b = blockIdx.x;
    const int tid = threadIdx.x;

    if (tid < 64)       xu[tid] = g_ncomb[b * 64 + tid];
    else if (tid < 128) xu[tid] = g_ecomb[b * 64 + (tid - 64)];
    else if (tid < 192) xu[tid] = grepr[b * 64 + (tid - 128)];
    else                xu[tid] = h_in[b * 64 + (tid - 192)];
    __syncthreads();

    float a = bih[tid] + bhh[tid];
    const float* wih_row = Wih + (size_t)tid * 192;
    #pragma unroll 8
    for (int k4 = 0; k4 < 48; ++k4) {
        float4 w = *(const float4*)&wih_row[k4 * 4];
        a += w.x * xu[k4 * 4] + w.y * xu[k4 * 4 + 1] + w.z * xu[k4 * 4 + 2] + w.w * xu[k4 * 4 + 3];
    }
    const float* whh_row = Whh + (size_t)tid * 64;
    #pragma unroll 8
    for (int k4 = 0; k4 < 16; ++k4) {
        float4 w = *(const float4*)&whh_row[k4 * 4];
        a += w.x * xu[192 + k4 * 4] + w.y * xu[192 + k4 * 4 + 1]
           + w.z * xu[192 + k4 * 4 + 2] + w.w * xu[192 + k4 * 4 + 3];
    }
    gs[tid] = a;
    __syncthreads();

    if (tid < 64) {
        float gi = gs[tid], gf = gs[64 + tid], gg = gs[128 + tid], go = gs[192 + tid];
        float c2 = sigm(gf) * c_in[b * 64 + tid] + sigm(gi) * tanh_(gg);
        float h = sigm(go) * tanh_(c2);
        out_r[b * 64 + tid] = fmaxf(h, 0.f);
        out_h[b * 64 + tid] = h;
        out_c[b * 64 + tid] = c2;
    }
}

extern "C" void kernel_launch(void* const* d_in, const int* in_sizes, int n_in,
                              void* d_out, int out_size)
{
    const float* edge_feat  = (const float*)d_in[0];
    const float* node_feat  = (const float*)d_in[1];
    const float* g_repr     = (const float*)d_in[2];
    const float* edge_h     = (const float*)d_in[3];
    const float* edge_c     = (const float*)d_in[4];
    const float* node_h     = (const float*)d_in[5];
    const float* node_c     = (const float*)d_in[6];
    const float* graph_h    = (const float*)d_in[7];
    const float* graph_c    = (const float*)d_in[8];
    const float* Wih_e      = (const float*)d_in[9];
    const float* Whh_e      = (const float*)d_in[10];
    const float* bih_e      = (const float*)d_in[11];
    const float* bhh_e      = (const float*)d_in[12];
    const float* Wih_n      = (const float*)d_in[13];
    const float* Whh_n      = (const float*)d_in[14];
    const float* bih_n      = (const float*)d_in[15];
    const float* bhh_n      = (const float*)d_in[16];
    const float* Wih_u      = (const float*)d_in[17];
    const float* Whh_u      = (const float*)d_in[18];
    const float* bih_u      = (const float*)d_in[19];
    const float* bhh_u      = (const float*)d_in[20];
    const int*   src        = (const int*)d_in[21];
    const int*   dst        = (const int*)d_in[22];
    const int*   edge_graph = (const int*)d_in[23];
    const int*   node_graph = (const int*)d_in[24];

    float* out = (float*)d_out;
    const size_t ED = (size_t)E_ * 64;
    const size_t ND = (size_t)NN_ * 64;
    const size_t BD = (size_t)B_ * 64;
    float* e_out = out;
    float* h_e   = out + ED;
    float* c_e   = out + 2 * ED;
    float* n_out = out + 3 * ED;
    float* h_n   = n_out + ND;
    float* c_n   = n_out + 2 * ND;
    float* u_out = n_out + 3 * ND;
    float* h_u   = u_out + BD;
    float* c_u   = u_out + 2 * BD;

    cudaFuncSetAttribute(lstm_mma_kernel<0>, cudaFuncAttributeMaxDynamicSharedMemorySize, SMEM_SZ);
    cudaFuncSetAttribute(lstm_mma_kernel<1>, cudaFuncAttributeMaxDynamicSharedMemorySize, SMEM_SZ);
    cudaFuncSetAttribute(gpre_kernel, cudaFuncAttributeMaxDynamicSharedMemorySize, SMEM_SZ);

    // 1) prep + weight transforms
    prep_kernel<<<(int)(((size_t)E_ * 64 / 8 + 255) / 256), 256>>>(edge_feat, edge_h, node_feat, node_h);
    splitw_kernel<<<256, 256>>>(Wih_e, Whh_e, Wih_n, Whh_n);
    gbias_kernel<<<B_, 256>>>(g_repr, Wih_e, Wih_n);

    // 2) per-node pre-GEMM: G = [nf@W1 | nf@W2]
    gpre_kernel<<<((NN_ + 63) / 64) * 4, 256, SMEM_SZ>>>();

    // 3) edge LSTM (K=128; src/dst terms gathered from g_G) + mailbox + e_comb
    lstm_mma_kernel<0><<<(E_ / 64) * 2, 256, SMEM_SZ>>>(
        edge_c, bih_e, bhh_e, src, dst, edge_graph, e_out, h_e, c_e, E_);

    // 4) convert mail, then node LSTM + n_comb
    split_mail_kernel<<<(NN_ * 64 / 8 + 255) / 256, 256>>>();
    lstm_mma_kernel<1><<<((NN_ + 63) / 64) * 2, 256, SMEM_SZ>>>(
        node_c, bih_n, bhh_n, nullptr, nullptr, node_graph, n_out, h_n, c_n, NN_);

    // 5) graph LSTM
    graph_lstm_kernel<<<B_, 256>>>(
        g_repr, graph_h, graph_c,
        Wih_u, Whh_u, bih_u, bhh_u,
        u_out, h_u, c_u);
}